// round 6
// baseline (speedup 1.0000x reference)
#include <cuda_runtime.h>
#include <cuda_bf16.h>
#include <math.h>
#include <stdint.h>

// Problem constants
#define NTOK   32768
#define DIM    512
#define NOPS   8

// GEMM tiling
#define BM 128
#define BN 128
#define BK 64                  // k elems per chunk = 128 bytes/row (SW128 atom)
#define NCHUNK (DIM / BK)      // 8
#define MAX_TILES 264
#define PERM_SIZE (MAX_TILES * BM)
#define THREADS 512

// SMEM per stage: A_hi 16K, A_lo 16K, B_hi 16K, B_lo 16K = 64K; two stages.
#define A_HI 0
#define A_LO 16384
#define B_HI 32768
#define B_LO 49152
#define STAGE 65536
#define SMEM_DYN (2 * STAGE + 1024)

#define SW128(o) ((o) ^ (((o) >> 3) & 0x70))

// ---------------- device scratch ----------------
__device__ int g_route[NTOK];
__device__ int g_cursor[NOPS];
__device__ int g_base[NOPS];
__device__ int g_perm[PERM_SIZE];
__device__ int g_tile_op[MAX_TILES];
__device__ int g_tile_row[MAX_TILES];
__device__ int g_ntiles;

__device__ __nv_bfloat16 g_Whi[NOPS * DIM * DIM];
__device__ __nv_bfloat16 g_Wlo[NOPS * DIM * DIM];

// ---------------- PTX helpers ----------------
__device__ __forceinline__ uint32_t smem_u32(const void* p) {
    uint32_t a;
    asm("{ .reg .u64 t; cvta.to.shared.u64 t, %1; cvt.u32.u64 %0, t; }" : "=r"(a) : "l"(p));
    return a;
}
__device__ __forceinline__ void cp_async16(uint32_t dst, const void* src) {
    asm volatile("cp.async.cg.shared.global [%0], [%1], 16;" :: "r"(dst), "l"(src) : "memory");
}
__device__ __forceinline__ void cp_commit() {
    asm volatile("cp.async.commit_group;" ::: "memory");
}
template <int N>
__device__ __forceinline__ void cp_wait() {
    asm volatile("cp.async.wait_group %0;" :: "n"(N) : "memory");
}
__device__ __forceinline__ void ldsm_x4(uint32_t& r0, uint32_t& r1, uint32_t& r2, uint32_t& r3,
                                        uint32_t addr) {
    asm volatile("ldmatrix.sync.aligned.m8n8.x4.shared.b16 {%0,%1,%2,%3}, [%4];"
                 : "=r"(r0), "=r"(r1), "=r"(r2), "=r"(r3) : "r"(addr));
}
__device__ __forceinline__ void hmma(float* c, const uint32_t* a, const uint32_t* b) {
    asm volatile(
        "mma.sync.aligned.m16n8k16.row.col.f32.bf16.bf16.f32 "
        "{%0,%1,%2,%3}, {%4,%5,%6,%7}, {%8,%9}, {%0,%1,%2,%3};"
        : "+f"(c[0]), "+f"(c[1]), "+f"(c[2]), "+f"(c[3])
        : "r"(a[0]), "r"(a[1]), "r"(a[2]), "r"(a[3]), "r"(b[0]), "r"(b[1]));
}

// ---------------- aux kernels ----------------

// W split to bf16 hi/lo + routing decision (independent index spaces, no ordering dep)
__global__ void wsplit_route_kernel(const float* __restrict__ W,
                                    const float* __restrict__ logits,
                                    const float* __restrict__ gumbel) {
    int i = blockIdx.x * blockDim.x + threadIdx.x;    // 0 .. 524287
    float4 w = ((const float4*)W)[i];
    float in[4] = {w.x, w.y, w.z, w.w};
    __nv_bfloat16 hb[4], lb[4];
#pragma unroll
    for (int j = 0; j < 4; j++) {
        hb[j] = __float2bfloat16(in[j]);
        lb[j] = __float2bfloat16(in[j] - __bfloat162float(hb[j]));
    }
    *(uint2*)&g_Whi[(size_t)i * 4] = *(uint2*)hb;
    *(uint2*)&g_Wlo[(size_t)i * 4] = *(uint2*)lb;

    if (i < NTOK) {
        float best = -INFINITY;
        int bi = 0;
#pragma unroll
        for (int k = 0; k < NOPS; k++) {
            float v = logits[i * NOPS + k] + gumbel[i * NOPS + k];
            if (v > best) { best = v; bi = k; }
        }
        g_route[i] = bi;
    }
}

// single block: count routes, build bases + tile metadata, zero cursors, mark padding
__global__ void scan_kernel() {
    __shared__ int cnt[NOPS * 8];        // 8 replicas to spread smem atomics
    __shared__ int s_base[NOPS], s_tb[NOPS + 1], s_cnt[NOPS];
    const int tid = threadIdx.x;
    if (tid < NOPS * 8) cnt[tid] = 0;
    __syncthreads();
    const int rep = (tid & 7) * NOPS;
    for (int t = tid; t < NTOK; t += 256)
        atomicAdd(&cnt[rep + g_route[t]], 1);
    __syncthreads();
    if (tid == 0) {
        int off = 0, tl = 0;
        for (int g = 0; g < NOPS; g++) {
            int c = 0;
            for (int rs = 0; rs < 8; rs++) c += cnt[rs * NOPS + g];
            s_cnt[g] = c;
            s_base[g] = off; g_base[g] = off;
            g_cursor[g] = 0;
            s_tb[g] = tl;
            int nt = (c + BM - 1) / BM;
            tl += nt; off += nt * BM;
        }
        s_tb[NOPS] = tl;
        g_ntiles = tl;
    }
    __syncthreads();
    const int ntl = s_tb[NOPS];
    for (int tile = tid; tile < ntl; tile += 256) {
        int g = 0;
        while (tile >= s_tb[g + 1]) g++;
        g_tile_op[tile] = g;
        g_tile_row[tile] = s_base[g] + (tile - s_tb[g]) * BM;
    }
    // padding rows -> -1
    for (int g = 0; g < NOPS; g++) {
        int c = s_cnt[g];
        int start = s_base[g] + c;
        int end   = s_base[g] + ((c + BM - 1) / BM) * BM;
        for (int p = start + tid; p < end; p += 256) g_perm[p] = -1;
    }
}

__global__ void scatter_kernel() {
    int t = blockIdx.x * blockDim.x + threadIdx.x;
    if (t >= NTOK) return;
    int op = g_route[t];
    int pos = atomicAdd(&g_cursor[op], 1);
    g_perm[g_base[op] + pos] = t;
}

__device__ __forceinline__ float apply_act(int op, float h) {
    switch (op) {
        case 0:  return 0.5f * h * (1.0f + erff(h * 0.7071067811865476f));
        case 1:  return fmaxf(h, 0.0f);
        case 2:  { float r = fmaxf(h, 0.0f); return r * r; }
        case 3:  return h / (1.0f + expf(-h));
        case 4:  return tanhf(h);
        case 5:  return 1.0f / (1.0f + expf(-h));
        case 6:  return h;
        default: return -h;
    }
}

__device__ __forceinline__ uint32_t pack_hi2(float a, float b, float& ra, float& rb) {
    __nv_bfloat16 ha = __float2bfloat16(a), hb = __float2bfloat16(b);
    ra = a - __bfloat162float(ha);
    rb = b - __bfloat162float(hb);
    return (uint32_t)__bfloat16_as_ushort(ha) | ((uint32_t)__bfloat16_as_ushort(hb) << 16);
}
__device__ __forceinline__ uint32_t pack_bf2(float a, float b) {
    return (uint32_t)__bfloat16_as_ushort(__float2bfloat16(a)) |
           ((uint32_t)__bfloat16_as_ushort(__float2bfloat16(b)) << 16);
}

// ---------------- fused-convert HMMA grouped GEMM ----------------
// 512 threads = 16 warps (4 M x 4 N), warp tile 32x32.
// Per k-chunk: A fp32 gathered + split in-kernel; acc += Ah*Wh + Ah*Wl + Al*Wh.
__global__ __launch_bounds__(THREADS, 1)
void gemm_kernel(const float* __restrict__ x, float* __restrict__ out) {
    extern __shared__ char dsm[];
    const int bx = blockIdx.x;
    if (bx >= g_ntiles) return;

    const int op   = g_tile_op[bx];
    const int row0 = g_tile_row[bx];
    const int n0   = blockIdx.y * BN;
    const int tid  = threadIdx.x;
    const int wid  = tid >> 5;
    const int lid  = tid & 31;
    const int wm   = wid >> 2;     // 0..3
    const int wn   = wid & 3;      // 0..3

    char* sbase = (char*)(((uintptr_t)dsm + 1023) & ~(uintptr_t)1023);
    const uint32_t sb = smem_u32(sbase);

    // ---- A gather pointers + swizzled STS offsets (4 row-units per thread)
    const int col16 = tid & 15;
    const float* aptr[4];
    uint32_t sA[4];
#pragma unroll
    for (int j = 0; j < 4; j++) {
        int row = (tid >> 4) + j * 32;
        int tok = g_perm[row0 + row];
        aptr[j] = (tok >= 0) ? (x + (size_t)tok * DIM + col16 * 4) : nullptr;
        sA[j] = SW128((uint32_t)(row * 128 + col16 * 8));
    }

    // ---- B cp.async setup (2 units per thread per tile)
    const __nv_bfloat16* __restrict__ Wh = g_Whi + (size_t)op * DIM * DIM + (size_t)n0 * DIM;
    const __nv_bfloat16* __restrict__ Wl = g_Wlo + (size_t)op * DIM * DIM + (size_t)n0 * DIM;
    uint32_t sB[2];
    int bsrc[2];
#pragma unroll
    for (int j = 0; j < 2; j++) {
        int u = tid + j * 512;
        int r = u >> 3, ks = u & 7;
        sB[j] = SW128((uint32_t)(r * 128 + ks * 16));
        bsrc[j] = r * DIM + ks * 8;
    }

    // ---- ldmatrix addressing
    const int a_row = wm * 32 + (lid & 15);
    const uint32_t a_rowoff = (uint32_t)(a_row * 128);
    const uint32_t a_mask = (uint32_t)((lid & 7) << 4);
    const uint32_t a_col0 = (uint32_t)((lid >> 4) << 4);
    const int b_row = wn * 32 + (lid & 7) + ((lid >> 4) << 3);
    const uint32_t b_rowoff = (uint32_t)(b_row * 128);
    const uint32_t b_mask = (uint32_t)((lid & 7) << 4);
    const uint32_t b_col0 = (uint32_t)(((lid >> 3) & 1) << 4);

    float acc[2][4][4];
#pragma unroll
    for (int i = 0; i < 2; i++)
#pragma unroll
        for (int j = 0; j < 4; j++)
#pragma unroll
            for (int q = 0; q < 4; q++) acc[i][j][q] = 0.0f;

    float4 areg[4];
    auto ldgA = [&](int kc) {
#pragma unroll
        for (int j = 0; j < 4; j++)
            areg[j] = aptr[j] ? *(const float4*)(aptr[j] + kc * BK)
                              : make_float4(0.f, 0.f, 0.f, 0.f);
    };
    auto stsA = [&](int s) {
        char* stage = sbase + s * STAGE;
#pragma unroll
        for (int j = 0; j < 4; j++) {
            float rx, ry, rz, rw;
            uint2 hw, lw;
            hw.x = pack_hi2(areg[j].x, areg[j].y, rx, ry);
            hw.y = pack_hi2(areg[j].z, areg[j].w, rz, rw);
            lw.x = pack_bf2(rx, ry);
            lw.y = pack_bf2(rz, rw);
            *(uint2*)(stage + A_HI + sA[j]) = hw;
            *(uint2*)(stage + A_LO + sA[j]) = lw;
        }
    };
    auto cpB = [&](int kc, int s) {
        uint32_t stage = sb + s * STAGE;
#pragma unroll
        for (int j = 0; j < 2; j++) {
            cp_async16(stage + B_HI + sB[j], Wh + bsrc[j] + kc * BK);
            cp_async16(stage + B_LO + sB[j], Wl + bsrc[j] + kc * BK);
        }
        cp_commit();
    };

    ldgA(0);
    cpB(0, 0);

    for (int i = 0; i < NCHUNK; i++) {
        const int s = i & 1;
        stsA(s);
        if (i + 1 < NCHUNK) ldgA(i + 1);
        cp_wait<0>();
        __syncthreads();
        if (i + 1 < NCHUNK) cpB(i + 1, 1 - s);

        const uint32_t stg = sb + s * STAGE;
        const uint32_t ah_base = stg + A_HI + a_rowoff;
        const uint32_t al_base = stg + A_LO + a_rowoff;
        const uint32_t bh_base = stg + B_HI + b_rowoff;
        const uint32_t bl_base = stg + B_LO + b_rowoff;

#pragma unroll
        for (int kk = 0; kk < 4; kk++) {
            const uint32_t ac = (a_col0 + kk * 32) ^ a_mask;
            const uint32_t bc = (b_col0 + kk * 32) ^ b_mask;
            uint32_t ah[2][4], al[2][4], bh[4][2], bl[4][2];
#pragma unroll
            for (int mi = 0; mi < 2; mi++) {
                ldsm_x4(ah[mi][0], ah[mi][1], ah[mi][2], ah[mi][3],
                        ah_base + mi * 2048 + ac);
                ldsm_x4(al[mi][0], al[mi][1], al[mi][2], al[mi][3],
                        al_base + mi * 2048 + ac);
            }
#pragma unroll
            for (int nb = 0; nb < 2; nb++) {
                ldsm_x4(bh[nb * 2][0], bh[nb * 2][1], bh[nb * 2 + 1][0], bh[nb * 2 + 1][1],
                        bh_base + nb * 2048 + bc);
                ldsm_x4(bl[nb * 2][0], bl[nb * 2][1], bl[nb * 2 + 1][0], bl[nb * 2 + 1][1],
                        bl_base + nb * 2048 + bc);
            }
#pragma unroll
            for (int mi = 0; mi < 2; mi++)
#pragma unroll
                for (int ni = 0; ni < 4; ni++) {
                    hmma(acc[mi][ni], ah[mi], bh[ni]);
                    hmma(acc[mi][ni], ah[mi], bl[ni]);
                    hmma(acc[mi][ni], al[mi], bh[ni]);
                }
        }
        __syncthreads();
    }

    // epilogue: activation + scatter to original token rows
    const int r = lid >> 2;
    const int c = (lid & 3) * 2;
#pragma unroll
    for (int mi = 0; mi < 2; mi++) {
        const int m_lo = wm * 32 + mi * 16 + r;
        const int tok_lo = g_perm[row0 + m_lo];
        const int tok_hi = g_perm[row0 + m_lo + 8];
        float* o_lo = (tok_lo >= 0) ? (out + (size_t)tok_lo * DIM + n0) : nullptr;
        float* o_hi = (tok_hi >= 0) ? (out + (size_t)tok_hi * DIM + n0) : nullptr;
#pragma unroll
        for (int ni = 0; ni < 4; ni++) {
            const int n = wn * 32 + ni * 8 + c;
            if (o_lo) {
                float2 v;
                v.x = apply_act(op, acc[mi][ni][0]);
                v.y = apply_act(op, acc[mi][ni][1]);
                *(float2*)(o_lo + n) = v;
            }
            if (o_hi) {
                float2 v;
                v.x = apply_act(op, acc[mi][ni][2]);
                v.y = apply_act(op, acc[mi][ni][3]);
                *(float2*)(o_hi + n) = v;
            }
        }
    }
}

// ---------------- launch ----------------
extern "C" void kernel_launch(void* const* d_in, const int* in_sizes, int n_in,
                              void* d_out, int out_size) {
    const float* x      = (const float*)d_in[0];
    const float* logits = (const float*)d_in[1];
    const float* gumbel = (const float*)d_in[2];
    const float* W      = (const float*)d_in[3];
    float* out          = (float*)d_out;

    cudaFuncSetAttribute(gemm_kernel, cudaFuncAttributeMaxDynamicSharedMemorySize, SMEM_DYN);

    wsplit_route_kernel<<<(NOPS * DIM * DIM / 4 + 255) / 256, 256>>>(W, logits, gumbel);
    scan_kernel<<<1, 256>>>();
    scatter_kernel<<<(NTOK + 255) / 256, 256>>>();

    dim3 grid(MAX_TILES, DIM / BN);
    gemm_kernel<<<grid, THREADS, SMEM_DYN>>>(x, out);
}

// round 7
// speedup vs baseline: 1.0675x; 1.0675x over previous
#include <cuda_runtime.h>
#include <cuda_bf16.h>
#include <math.h>
#include <stdint.h>

// Problem constants
#define NTOK   32768
#define DIM    512
#define NOPS   8

// GEMM tiling (round-4 proven config)
#define BM 128
#define BN 128
#define BK 64                  // k elems per chunk = 128 bytes/row (SW128 atom)
#define NCHUNK (DIM / BK)      // 8
#define NPASS 3                // hi*hi, hi*lo, lo*hi
#define NITER (NPASS * NCHUNK) // 24
#define MAX_TILES 264
#define PERM_SIZE (MAX_TILES * BM)

// SMEM: A[2] then B[2], 16KB each
#define SMEM_A0 0
#define SMEM_A1 16384
#define SMEM_B0 32768
#define SMEM_B1 49152
#define SMEM_DYN (65536 + 1024)

#define SW128(o) ((o) ^ (((o) >> 3) & 0x70))

// ---------------- device scratch ----------------
__device__ int g_route[NTOK];
__device__ int g_cursor[NOPS];
__device__ int g_base[NOPS];
__device__ int g_cnt[NOPS];
__device__ int g_perm[PERM_SIZE];
__device__ int g_tile_op[MAX_TILES];
__device__ int g_tile_row[MAX_TILES];
__device__ int g_ntiles;

__device__ __nv_bfloat16 g_Whi[NOPS * DIM * DIM];
__device__ __nv_bfloat16 g_Wlo[NOPS * DIM * DIM];
__device__ __nv_bfloat16 g_Ahi[(size_t)PERM_SIZE * DIM];
__device__ __nv_bfloat16 g_Alo[(size_t)PERM_SIZE * DIM];

// ---------------- PTX helpers ----------------
__device__ __forceinline__ uint32_t smem_u32(const void* p) {
    uint32_t a;
    asm("{ .reg .u64 t; cvta.to.shared.u64 t, %1; cvt.u32.u64 %0, t; }" : "=r"(a) : "l"(p));
    return a;
}
__device__ __forceinline__ void cp_async16(uint32_t dst, const void* src) {
    asm volatile("cp.async.cg.shared.global [%0], [%1], 16;" :: "r"(dst), "l"(src) : "memory");
}
__device__ __forceinline__ void cp_commit() {
    asm volatile("cp.async.commit_group;" ::: "memory");
}
template <int N>
__device__ __forceinline__ void cp_wait() {
    asm volatile("cp.async.wait_group %0;" :: "n"(N) : "memory");
}
__device__ __forceinline__ void ldsm_x4(uint32_t& r0, uint32_t& r1, uint32_t& r2, uint32_t& r3,
                                        uint32_t addr) {
    asm volatile("ldmatrix.sync.aligned.m8n8.x4.shared.b16 {%0,%1,%2,%3}, [%4];"
                 : "=r"(r0), "=r"(r1), "=r"(r2), "=r"(r3) : "r"(addr));
}
__device__ __forceinline__ void hmma(float* c, const uint32_t* a, const uint32_t* b) {
    asm volatile(
        "mma.sync.aligned.m16n8k16.row.col.f32.bf16.bf16.f32 "
        "{%0,%1,%2,%3}, {%4,%5,%6,%7}, {%8,%9}, {%0,%1,%2,%3};"
        : "+f"(c[0]), "+f"(c[1]), "+f"(c[2]), "+f"(c[3])
        : "r"(a[0]), "r"(a[1]), "r"(a[2]), "r"(a[3]), "r"(b[0]), "r"(b[1]));
}

// ---------------- aux kernels ----------------

// W split to bf16 hi/lo + routing decision
__global__ void wsplit_route_kernel(const float* __restrict__ W,
                                    const float* __restrict__ logits,
                                    const float* __restrict__ gumbel) {
    int i = blockIdx.x * blockDim.x + threadIdx.x;    // 0 .. 524287
    float4 w = ((const float4*)W)[i];
    float in[4] = {w.x, w.y, w.z, w.w};
    __nv_bfloat16 hb[4], lb[4];
#pragma unroll
    for (int j = 0; j < 4; j++) {
        hb[j] = __float2bfloat16(in[j]);
        lb[j] = __float2bfloat16(in[j] - __bfloat162float(hb[j]));
    }
    *(uint2*)&g_Whi[(size_t)i * 4] = *(uint2*)hb;
    *(uint2*)&g_Wlo[(size_t)i * 4] = *(uint2*)lb;

    if (i < NTOK) {
        float best = -INFINITY;
        int bi = 0;
#pragma unroll
        for (int k = 0; k < NOPS; k++) {
            float v = logits[i * NOPS + k] + gumbel[i * NOPS + k];
            if (v > best) { best = v; bi = k; }
        }
        g_route[i] = bi;
    }
}

// single block: count routes, build bases + tile metadata, zero cursors, mark padding perm
__global__ void scan_kernel() {
    __shared__ int cnt[NOPS * 8];
    __shared__ int s_base[NOPS], s_tb[NOPS + 1], s_cnt[NOPS];
    const int tid = threadIdx.x;
    if (tid < NOPS * 8) cnt[tid] = 0;
    __syncthreads();
    const int rep = (tid & 7) * NOPS;
    for (int t = tid; t < NTOK; t += 256)
        atomicAdd(&cnt[rep + g_route[t]], 1);
    __syncthreads();
    if (tid == 0) {
        int off = 0, tl = 0;
        for (int g = 0; g < NOPS; g++) {
            int c = 0;
            for (int rs = 0; rs < 8; rs++) c += cnt[rs * NOPS + g];
            s_cnt[g] = c; g_cnt[g] = c;
            s_base[g] = off; g_base[g] = off;
            g_cursor[g] = 0;
            s_tb[g] = tl;
            int nt = (c + BM - 1) / BM;
            tl += nt; off += nt * BM;
        }
        s_tb[NOPS] = tl;
        g_ntiles = tl;
    }
    __syncthreads();
    const int ntl = s_tb[NOPS];
    for (int tile = tid; tile < ntl; tile += 256) {
        int g = 0;
        while (tile >= s_tb[g + 1]) g++;
        g_tile_op[tile] = g;
        g_tile_row[tile] = s_base[g] + (tile - s_tb[g]) * BM;
    }
    for (int g = 0; g < NOPS; g++) {
        int c = s_cnt[g];
        int start = s_base[g] + c;
        int end   = s_base[g] + ((c + BM - 1) / BM) * BM;
        for (int p = start + tid; p < end; p += 256) g_perm[p] = -1;
    }
}

__device__ __forceinline__ uint32_t pack_hi2(float a, float b, float& ra, float& rb) {
    __nv_bfloat16 ha = __float2bfloat16(a), hb = __float2bfloat16(b);
    ra = a - __bfloat162float(ha);
    rb = b - __bfloat162float(hb);
    return (uint32_t)__bfloat16_as_ushort(ha) | ((uint32_t)__bfloat16_as_ushort(hb) << 16);
}
__device__ __forceinline__ uint32_t pack_bf2(float a, float b) {
    return (uint32_t)__bfloat16_as_ushort(__float2bfloat16(a)) |
           ((uint32_t)__bfloat16_as_ushort(__float2bfloat16(b)) << 16);
}

// merged scatter + A-convert: one warp per token; extra warps zero padding rows
#define PAD_WARPS 1024
__global__ void scatter_convert_kernel(const float* __restrict__ x) {
    const int w    = (blockIdx.x * blockDim.x + threadIdx.x) >> 5;
    const int lane = threadIdx.x & 31;

    if (w < NTOK) {
        const int t = w;
        int row = 0;
        if (lane == 0) {
            int op  = g_route[t];
            int pos = atomicAdd(&g_cursor[op], 1);
            row = g_base[op] + pos;
            g_perm[row] = t;
        }
        row = __shfl_sync(0xffffffffu, row, 0);
        const float4* src = (const float4*)(x + (size_t)t * DIM);
        __nv_bfloat16* dh = g_Ahi + (size_t)row * DIM;
        __nv_bfloat16* dl = g_Alo + (size_t)row * DIM;
#pragma unroll
        for (int j = 0; j < 4; j++) {
            const int c4 = j * 32 + lane;          // float4 index 0..127
            float4 v = src[c4];
            float rx, ry, rz, rw;
            uint2 hw, lw;
            hw.x = pack_hi2(v.x, v.y, rx, ry);
            hw.y = pack_hi2(v.z, v.w, rz, rw);
            lw.x = pack_bf2(rx, ry);
            lw.y = pack_bf2(rz, rw);
            *(uint2*)(dh + c4 * 4) = hw;
            *(uint2*)(dl + c4 * 4) = lw;
        }
    } else {
        const int p = w - NTOK;
        if (p >= PAD_WARPS) return;
        const int g = p >> 7, j = p & 127;
        const int cnt  = g_cnt[g];
        const int base = g_base[g];
        const int row  = base + cnt + j;
        const int end  = base + ((cnt + BM - 1) / BM) * BM;
        if (row < end) {
            uint2 z = make_uint2(0u, 0u);
            __nv_bfloat16* dh = g_Ahi + (size_t)row * DIM;
            __nv_bfloat16* dl = g_Alo + (size_t)row * DIM;
#pragma unroll
            for (int q = 0; q < 4; q++) {
                *(uint2*)(dh + (q * 32 + lane) * 4) = z;
                *(uint2*)(dl + (q * 32 + lane) * 4) = z;
            }
        }
    }
}

__device__ __forceinline__ float apply_act(int op, float h) {
    switch (op) {
        case 0:  return 0.5f * h * (1.0f + erff(h * 0.7071067811865476f));
        case 1:  return fmaxf(h, 0.0f);
        case 2:  { float r = fmaxf(h, 0.0f); return r * r; }
        case 3:  return h / (1.0f + expf(-h));
        case 4:  return tanhf(h);
        case 5:  return 1.0f / (1.0f + expf(-h));
        case 6:  return h;
        default: return -h;
    }
}

// ---------------- HMMA grouped GEMM (round-4 config: 256 thr, 3 CTAs/SM) ----------------
__global__ __launch_bounds__(256)
void gemm_kernel(float* __restrict__ out) {
    extern __shared__ char dsm[];
    const int bx = blockIdx.x;
    if (bx >= g_ntiles) return;

    const int op   = g_tile_op[bx];
    const int row0 = g_tile_row[bx];
    const int n0   = blockIdx.y * BN;
    const int tid  = threadIdx.x;
    const int wid  = tid >> 5;
    const int lid  = tid & 31;
    const int wm   = wid >> 2;     // 0..1
    const int wn   = wid & 3;      // 0..3

    char* sbase = (char*)(((uintptr_t)dsm + 1023) & ~(uintptr_t)1023);
    const uint32_t sb = smem_u32(sbase);

    const __nv_bfloat16* __restrict__ Wh = g_Whi + (size_t)op * DIM * DIM;
    const __nv_bfloat16* __restrict__ Wl = g_Wlo + (size_t)op * DIM * DIM;
    const __nv_bfloat16* Apass[NPASS] = {g_Ahi, g_Ahi, g_Alo};
    const __nv_bfloat16* Bpass[NPASS] = {Wh, Wl, Wh};

    // store mapping: 1024 16B units; r = sid>>3 (row), ks = sid&7 (16B col)
    const int lr = tid >> 3;
    const int ks = tid & 7;
    const uint32_t sw_col = (uint32_t)(ks * 16);

    // ldmatrix addressing: addr = row_base + (col ^ mask), mask = (row&7)<<4
    const int a_row = wm * 64 + (lid & 15);
    const uint32_t a_rowbase = sb + SMEM_A0 + (uint32_t)(a_row * 128);
    const uint32_t a_mask = (uint32_t)((a_row & 7) << 4);
    const uint32_t a_col0 = (uint32_t)((lid >> 4) << 4);
    const int b_row = wn * 32 + (lid & 7) + ((lid >> 4) << 3);
    const uint32_t b_rowbase = sb + SMEM_B0 + (uint32_t)(b_row * 128);
    const uint32_t b_mask = (uint32_t)((b_row & 7) << 4);
    const uint32_t b_col0 = (uint32_t)(((lid >> 3) & 1) << 4);

    float acc[4][4][4];
#pragma unroll
    for (int i = 0; i < 4; i++)
#pragma unroll
        for (int j = 0; j < 4; j++)
#pragma unroll
            for (int q = 0; q < 4; q++) acc[i][j][q] = 0.0f;

    auto load_chunk = [&](int c, int s) {
        const int p  = c >> 3;
        const int kc = c & 7;
        const __nv_bfloat16* Ag = Apass[p] + (size_t)row0 * DIM + kc * BK;
        const __nv_bfloat16* Bg = Bpass[p] + (size_t)n0 * DIM + kc * BK;
        const uint32_t As = sb + (s ? SMEM_A1 : SMEM_A0);
        const uint32_t Bs = sb + (s ? SMEM_B1 : SMEM_B0);
#pragma unroll
        for (int j = 0; j < 4; j++) {
            int r = lr + j * 32;
            uint32_t soff = SW128((uint32_t)(r * 128) + sw_col);
            cp_async16(As + soff, Ag + (size_t)r * DIM + ks * 8);
            cp_async16(Bs + soff, Bg + (size_t)r * DIM + ks * 8);
        }
        cp_commit();
    };

    load_chunk(0, 0);
    load_chunk(1, 1);

    for (int i = 0; i < NITER; i++) {
        const int s = i & 1;
        cp_wait<1>();
        __syncthreads();

        const uint32_t As_base = a_rowbase + (s ? SMEM_A1 : 0);
        const uint32_t Bs_base = b_rowbase + (s ? (SMEM_B1 - SMEM_B0) : 0);

#pragma unroll
        for (int kk = 0; kk < 4; kk++) {
            const uint32_t a_col = (a_col0 + kk * 32) ^ a_mask;
            const uint32_t b_col = (b_col0 + kk * 32) ^ b_mask;
            uint32_t a[4][4];
            uint32_t b[4][2];
#pragma unroll
            for (int mi = 0; mi < 4; mi++)
                ldsm_x4(a[mi][0], a[mi][1], a[mi][2], a[mi][3],
                        As_base + mi * (16 * 128) + a_col);
#pragma unroll
            for (int nb = 0; nb < 2; nb++)
                ldsm_x4(b[nb * 2][0], b[nb * 2][1], b[nb * 2 + 1][0], b[nb * 2 + 1][1],
                        Bs_base + nb * (16 * 128) + b_col);
#pragma unroll
            for (int mi = 0; mi < 4; mi++)
#pragma unroll
                for (int ni = 0; ni < 4; ni++)
                    hmma(acc[mi][ni], a[mi], b[ni]);
        }

        __syncthreads();
        if (i + 2 < NITER) load_chunk(i + 2, s);
        else cp_commit();   // keep group count consistent for cp_wait<1>
    }

    // epilogue: activation + scatter to original token rows
    const int r = lid >> 2;
    const int c = (lid & 3) * 2;
#pragma unroll
    for (int mi = 0; mi < 4; mi++) {
        const int m_lo = wm * 64 + mi * 16 + r;
        const int tok_lo = g_perm[row0 + m_lo];
        const int tok_hi = g_perm[row0 + m_lo + 8];
        float* o_lo = (tok_lo >= 0) ? (out + (size_t)tok_lo * DIM + n0) : nullptr;
        float* o_hi = (tok_hi >= 0) ? (out + (size_t)tok_hi * DIM + n0) : nullptr;
#pragma unroll
        for (int ni = 0; ni < 4; ni++) {
            const int n = wn * 32 + ni * 8 + c;
            if (o_lo) {
                float2 v;
                v.x = apply_act(op, acc[mi][ni][0]);
                v.y = apply_act(op, acc[mi][ni][1]);
                *(float2*)(o_lo + n) = v;
            }
            if (o_hi) {
                float2 v;
                v.x = apply_act(op, acc[mi][ni][2]);
                v.y = apply_act(op, acc[mi][ni][3]);
                *(float2*)(o_hi + n) = v;
            }
        }
    }
}

// ---------------- launch ----------------
extern "C" void kernel_launch(void* const* d_in, const int* in_sizes, int n_in,
                              void* d_out, int out_size) {
    const float* x      = (const float*)d_in[0];
    const float* logits = (const float*)d_in[1];
    const float* gumbel = (const float*)d_in[2];
    const float* W      = (const float*)d_in[3];
    float* out          = (float*)d_out;

    cudaFuncSetAttribute(gemm_kernel, cudaFuncAttributeMaxDynamicSharedMemorySize, SMEM_DYN);

    wsplit_route_kernel<<<(NOPS * DIM * DIM / 4 + 255) / 256, 256>>>(W, logits, gumbel);
    scan_kernel<<<1, 256>>>();
    scatter_convert_kernel<<<((NTOK + PAD_WARPS) * 32) / 256, 256>>>(x);

    dim3 grid(MAX_TILES, DIM / BN);
    gemm_kernel<<<grid, 256, SMEM_DYN>>>(out);
}

// round 10
// speedup vs baseline: 1.0700x; 1.0024x over previous
#include <cuda_runtime.h>
#include <cuda_bf16.h>
#include <math.h>
#include <stdint.h>

// Problem constants
#define NTOK   32768
#define DIM    512
#define NOPS   8

// GEMM tiling
#define BM 128
#define BN 128
#define BK 64                  // k elems per chunk = 128 bytes/row (SW128 atom)
#define NCHUNK (DIM / BK)      // 8
#define NPASS 3                // hi*hi, hi*lo, lo*hi
#define NITER (NPASS * NCHUNK) // 24
#define MAX_TILES 264
#define PERM_SIZE (MAX_TILES * BM)

// SMEM: 3 stages x (A 16KB + B 16KB)
#define STAGE_BYTES 32768
#define B_OFF 16384
#define NSTAGE 3
#define SMEM_DYN (NSTAGE * STAGE_BYTES + 1024)

#define SW128(o) ((o) ^ (((o) >> 3) & 0x70))

// ---------------- device scratch ----------------
__device__ int g_route[NTOK];
__device__ int g_cursor[NOPS];
__device__ int g_base[NOPS];
__device__ int g_cnt[NOPS];
__device__ int g_perm[PERM_SIZE];
__device__ int g_tile_op[MAX_TILES];
__device__ int g_tile_row[MAX_TILES];
__device__ int g_ntiles;

__device__ __nv_bfloat16 g_Whi[NOPS * DIM * DIM];
__device__ __nv_bfloat16 g_Wlo[NOPS * DIM * DIM];
__device__ __nv_bfloat16 g_Ahi[(size_t)PERM_SIZE * DIM];
__device__ __nv_bfloat16 g_Alo[(size_t)PERM_SIZE * DIM];

// ---------------- PTX helpers ----------------
__device__ __forceinline__ uint32_t smem_u32(const void* p) {
    uint32_t a;
    asm("{ .reg .u64 t; cvta.to.shared.u64 t, %1; cvt.u32.u64 %0, t; }" : "=r"(a) : "l"(p));
    return a;
}
__device__ __forceinline__ void cp_async16(uint32_t dst, const void* src) {
    asm volatile("cp.async.cg.shared.global [%0], [%1], 16;" :: "r"(dst), "l"(src) : "memory");
}
__device__ __forceinline__ void cp_commit() {
    asm volatile("cp.async.commit_group;" ::: "memory");
}
template <int N>
__device__ __forceinline__ void cp_wait() {
    asm volatile("cp.async.wait_group %0;" :: "n"(N) : "memory");
}
__device__ __forceinline__ void ldsm_x4(uint32_t& r0, uint32_t& r1, uint32_t& r2, uint32_t& r3,
                                        uint32_t addr) {
    asm volatile("ldmatrix.sync.aligned.m8n8.x4.shared.b16 {%0,%1,%2,%3}, [%4];"
                 : "=r"(r0), "=r"(r1), "=r"(r2), "=r"(r3) : "r"(addr));
}
__device__ __forceinline__ void hmma(float* c, const uint32_t* a, const uint32_t* b) {
    asm volatile(
        "mma.sync.aligned.m16n8k16.row.col.f32.bf16.bf16.f32 "
        "{%0,%1,%2,%3}, {%4,%5,%6,%7}, {%8,%9}, {%0,%1,%2,%3};"
        : "+f"(c[0]), "+f"(c[1]), "+f"(c[2]), "+f"(c[3])
        : "r"(a[0]), "r"(a[1]), "r"(a[2]), "r"(a[3]), "r"(b[0]), "r"(b[1]));
}

// ---------------- aux kernels ----------------

__global__ void wsplit_route_kernel(const float* __restrict__ W,
                                    const float* __restrict__ logits,
                                    const float* __restrict__ gumbel) {
    int i = blockIdx.x * blockDim.x + threadIdx.x;    // 0 .. 524287
    float4 w = ((const float4*)W)[i];
    float in[4] = {w.x, w.y, w.z, w.w};
    __nv_bfloat16 hb[4], lb[4];
#pragma unroll
    for (int j = 0; j < 4; j++) {
        hb[j] = __float2bfloat16(in[j]);
        lb[j] = __float2bfloat16(in[j] - __bfloat162float(hb[j]));
    }
    *(uint2*)&g_Whi[(size_t)i * 4] = *(uint2*)hb;
    *(uint2*)&g_Wlo[(size_t)i * 4] = *(uint2*)lb;

    if (i < NTOK) {
        float best = -INFINITY;
        int bi = 0;
#pragma unroll
        for (int k = 0; k < NOPS; k++) {
            float v = logits[i * NOPS + k] + gumbel[i * NOPS + k];
            if (v > best) { best = v; bi = k; }
        }
        g_route[i] = bi;
    }
}

__global__ void scan_kernel() {
    __shared__ int cnt[NOPS * 8];
    __shared__ int s_base[NOPS], s_tb[NOPS + 1], s_cnt[NOPS];
    const int tid = threadIdx.x;
    if (tid < NOPS * 8) cnt[tid] = 0;
    __syncthreads();
    const int rep = (tid & 7) * NOPS;
    for (int t = tid; t < NTOK; t += 256)
        atomicAdd(&cnt[rep + g_route[t]], 1);
    __syncthreads();
    if (tid == 0) {
        int off = 0, tl = 0;
        for (int g = 0; g < NOPS; g++) {
            int c = 0;
            for (int rs = 0; rs < 8; rs++) c += cnt[rs * NOPS + g];
            s_cnt[g] = c; g_cnt[g] = c;
            s_base[g] = off; g_base[g] = off;
            g_cursor[g] = 0;
            s_tb[g] = tl;
            int nt = (c + BM - 1) / BM;
            tl += nt; off += nt * BM;
        }
        s_tb[NOPS] = tl;
        g_ntiles = tl;
    }
    __syncthreads();
    const int ntl = s_tb[NOPS];
    for (int tile = tid; tile < ntl; tile += 256) {
        int g = 0;
        while (tile >= s_tb[g + 1]) g++;
        g_tile_op[tile] = g;
        g_tile_row[tile] = s_base[g] + (tile - s_tb[g]) * BM;
    }
    for (int g = 0; g < NOPS; g++) {
        int c = s_cnt[g];
        int start = s_base[g] + c;
        int end   = s_base[g] + ((c + BM - 1) / BM) * BM;
        for (int p = start + tid; p < end; p += 256) g_perm[p] = -1;
    }
}

__device__ __forceinline__ uint32_t pack_hi2(float a, float b, float& ra, float& rb) {
    __nv_bfloat16 ha = __float2bfloat16(a), hb = __float2bfloat16(b);
    ra = a - __bfloat162float(ha);
    rb = b - __bfloat162float(hb);
    return (uint32_t)__bfloat16_as_ushort(ha) | ((uint32_t)__bfloat16_as_ushort(hb) << 16);
}
__device__ __forceinline__ uint32_t pack_bf2(float a, float b) {
    return (uint32_t)__bfloat16_as_ushort(__float2bfloat16(a)) |
           ((uint32_t)__bfloat16_as_ushort(__float2bfloat16(b)) << 16);
}

// merged scatter + A-convert: one warp per token; extra warps zero padding rows
#define PAD_WARPS 1024
__global__ void scatter_convert_kernel(const float* __restrict__ x) {
    const int w    = (blockIdx.x * blockDim.x + threadIdx.x) >> 5;
    const int lane = threadIdx.x & 31;

    if (w < NTOK) {
        const int t = w;
        int row = 0;
        if (lane == 0) {
            int op  = g_route[t];
            int pos = atomicAdd(&g_cursor[op], 1);
            row = g_base[op] + pos;
            g_perm[row] = t;
        }
        row = __shfl_sync(0xffffffffu, row, 0);
        const float4* src = (const float4*)(x + (size_t)t * DIM);
        __nv_bfloat16* dh = g_Ahi + (size_t)row * DIM;
        __nv_bfloat16* dl = g_Alo + (size_t)row * DIM;
#pragma unroll
        for (int j = 0; j < 4; j++) {
            const int c4 = j * 32 + lane;
            float4 v = src[c4];
            float rx, ry, rz, rw;
            uint2 hw, lw;
            hw.x = pack_hi2(v.x, v.y, rx, ry);
            hw.y = pack_hi2(v.z, v.w, rz, rw);
            lw.x = pack_bf2(rx, ry);
            lw.y = pack_bf2(rz, rw);
            *(uint2*)(dh + c4 * 4) = hw;
            *(uint2*)(dl + c4 * 4) = lw;
        }
    } else {
        const int p = w - NTOK;
        if (p >= PAD_WARPS) return;
        const int g = p >> 7, j = p & 127;
        const int cnt  = g_cnt[g];
        const int base = g_base[g];
        const int row  = base + cnt + j;
        const int end  = base + ((cnt + BM - 1) / BM) * BM;
        if (row < end) {
            uint2 z = make_uint2(0u, 0u);
            __nv_bfloat16* dh = g_Ahi + (size_t)row * DIM;
            __nv_bfloat16* dl = g_Alo + (size_t)row * DIM;
#pragma unroll
            for (int q = 0; q < 4; q++) {
                *(uint2*)(dh + (q * 32 + lane) * 4) = z;
                *(uint2*)(dl + (q * 32 + lane) * 4) = z;
            }
        }
    }
}

__device__ __forceinline__ float apply_act(int op, float h) {
    switch (op) {
        case 0:  return 0.5f * h * (1.0f + erff(h * 0.7071067811865476f));
        case 1:  return fmaxf(h, 0.0f);
        case 2:  { float r = fmaxf(h, 0.0f); return r * r; }
        case 3:  return h / (1.0f + expf(-h));
        case 4:  return tanhf(h);
        case 5:  return 1.0f / (1.0f + expf(-h));
        case 6:  return h;
        default: return -h;
    }
}

// ---------------- HMMA grouped GEMM: 3-stage pipeline, 1 barrier/iter ----------------
__global__ __launch_bounds__(256)
void gemm_kernel(float* __restrict__ out) {
    extern __shared__ char dsm[];
    const int bx = blockIdx.x;
    if (bx >= g_ntiles) return;

    const int op   = g_tile_op[bx];
    const int row0 = g_tile_row[bx];
    const int n0   = blockIdx.y * BN;
    const int tid  = threadIdx.x;
    const int wid  = tid >> 5;
    const int lid  = tid & 31;
    const int wm   = wid >> 2;     // 0..1
    const int wn   = wid & 3;      // 0..3

    char* sbase = (char*)(((uintptr_t)dsm + 1023) & ~(uintptr_t)1023);
    const uint32_t sb = smem_u32(sbase);

    const __nv_bfloat16* __restrict__ Wh = g_Whi + (size_t)op * DIM * DIM;
    const __nv_bfloat16* __restrict__ Wl = g_Wlo + (size_t)op * DIM * DIM;
    const __nv_bfloat16* Apass[NPASS] = {g_Ahi, g_Ahi, g_Alo};
    const __nv_bfloat16* Bpass[NPASS] = {Wh, Wl, Wh};

    // store mapping: 1024 16B units per stage half; r = sid>>3 (row), ks = sid&7
    const int lr = tid >> 3;
    const int ks = tid & 7;
    const uint32_t sw_col = (uint32_t)(ks * 16);

    // ldmatrix addressing: addr = stage + region + row*128 + (col ^ mask)
    const int a_row = wm * 64 + (lid & 15);
    const uint32_t a_rowoff = (uint32_t)(a_row * 128);
    const uint32_t a_mask = (uint32_t)((a_row & 7) << 4);
    const uint32_t a_col0 = (uint32_t)((lid >> 4) << 4);
    const int b_row = wn * 32 + (lid & 7) + ((lid >> 4) << 3);
    const uint32_t b_rowoff = (uint32_t)(B_OFF + b_row * 128);
    const uint32_t b_mask = (uint32_t)((b_row & 7) << 4);
    const uint32_t b_col0 = (uint32_t)(((lid >> 3) & 1) << 4);

    float acc[4][4][4];
#pragma unroll
    for (int i = 0; i < 4; i++)
#pragma unroll
        for (int j = 0; j < 4; j++)
#pragma unroll
            for (int q = 0; q < 4; q++) acc[i][j][q] = 0.0f;

    auto load_chunk = [&](int c, int s) {
        const int p  = c >> 3;
        const int kc = c & 7;
        const __nv_bfloat16* Ag = Apass[p] + (size_t)row0 * DIM + kc * BK;
        const __nv_bfloat16* Bg = Bpass[p] + (size_t)n0 * DIM + kc * BK;
        const uint32_t As = sb + s * STAGE_BYTES;
        const uint32_t Bs = As + B_OFF;
#pragma unroll
        for (int j = 0; j < 4; j++) {
            int r = lr + j * 32;
            uint32_t soff = SW128((uint32_t)(r * 128) + sw_col);
            cp_async16(As + soff, Ag + (size_t)r * DIM + ks * 8);
            cp_async16(Bs + soff, Bg + (size_t)r * DIM + ks * 8);
        }
        cp_commit();
    };

    load_chunk(0, 0);
    load_chunk(1, 1);

    int s = 0;
    for (int i = 0; i < NITER; i++) {
        cp_wait<1>();
        __syncthreads();
        // stage (i+2)%3 was last read at iteration i-1 -> safe to overwrite now
        if (i + 2 < NITER) {
            int s2 = s + 2; if (s2 >= NSTAGE) s2 -= NSTAGE;
            load_chunk(i + 2, s2);
        } else {
            cp_commit();   // keep group count consistent for cp_wait<1>
        }

        const uint32_t stg = sb + s * STAGE_BYTES;
        const uint32_t As_base = stg + a_rowoff;
        const uint32_t Bs_base = stg + b_rowoff;

#pragma unroll
        for (int kk = 0; kk < 4; kk++) {
            const uint32_t a_col = (a_col0 + kk * 32) ^ a_mask;
            const uint32_t b_col = (b_col0 + kk * 32) ^ b_mask;
            uint32_t a[4][4];
            uint32_t b[4][2];
#pragma unroll
            for (int mi = 0; mi < 4; mi++)
                ldsm_x4(a[mi][0], a[mi][1], a[mi][2], a[mi][3],
                        As_base + mi * (16 * 128) + a_col);
#pragma unroll
            for (int nb = 0; nb < 2; nb++)
                ldsm_x4(b[nb * 2][0], b[nb * 2][1], b[nb * 2 + 1][0], b[nb * 2 + 1][1],
                        Bs_base + nb * (16 * 128) + b_col);
#pragma unroll
            for (int mi = 0; mi < 4; mi++)
#pragma unroll
                for (int ni = 0; ni < 4; ni++)
                    hmma(acc[mi][ni], a[mi], b[ni]);
        }

        if (++s >= NSTAGE) s -= NSTAGE;
    }

    // epilogue: activation + scatter to original token rows
    const int r = lid >> 2;
    const int c = (lid & 3) * 2;
#pragma unroll
    for (int mi = 0; mi < 4; mi++) {
        const int m_lo = wm * 64 + mi * 16 + r;
        const int tok_lo = g_perm[row0 + m_lo];
        const int tok_hi = g_perm[row0 + m_lo + 8];
        float* o_lo = (tok_lo >= 0) ? (out + (size_t)tok_lo * DIM + n0) : nullptr;
        float* o_hi = (tok_hi >= 0) ? (out + (size_t)tok_hi * DIM + n0) : nullptr;
#pragma unroll
        for (int ni = 0; ni < 4; ni++) {
            const int n = wn * 32 + ni * 8 + c;
            if (o_lo) {
                float2 v;
                v.x = apply_act(op, acc[mi][ni][0]);
                v.y = apply_act(op, acc[mi][ni][1]);
                *(float2*)(o_lo + n) = v;
            }
            if (o_hi) {
                float2 v;
                v.x = apply_act(op, acc[mi][ni][2]);
                v.y = apply_act(op, acc[mi][ni][3]);
                *(float2*)(o_hi + n) = v;
            }
        }
    }
}

// ---------------- launch ----------------
extern "C" void kernel_launch(void* const* d_in, const int* in_sizes, int n_in,
                              void* d_out, int out_size) {
    const float* x      = (const float*)d_in[0];
    const float* logits = (const float*)d_in[1];
    const float* gumbel = (const float*)d_in[2];
    const float* W      = (const float*)d_in[3];
    float* out          = (float*)d_out;

    cudaFuncSetAttribute(gemm_kernel, cudaFuncAttributeMaxDynamicSharedMemorySize, SMEM_DYN);

    wsplit_route_kernel<<<(NOPS * DIM * DIM / 4 + 255) / 256, 256>>>(W, logits, gumbel);
    scan_kernel<<<1, 256>>>();
    scatter_convert_kernel<<<((NTOK + PAD_WARPS) * 32) / 256, 256>>>(x);

    dim3 grid(MAX_TILES, DIM / BN);
    gemm_kernel<<<grid, 256, SMEM_DYN>>>(out);
}

// round 12
// speedup vs baseline: 1.3368x; 1.2493x over previous
#include <cuda_runtime.h>
#include <cuda_bf16.h>
#include <math.h>
#include <stdint.h>

// Problem constants
#define NTOK   32768
#define DIM    512
#define NOPS   8

// GEMM tiling: single-pass tf32, BK=32 floats = 128B/row (SW128 atom)
#define BM 128
#define BN 128
#define BK 32
#define NCHUNK (DIM / BK)      // 16
#define NITER NCHUNK           // single pass
#define MAX_TILES 264
#define PERM_SIZE (MAX_TILES * BM)

// SMEM: 3 stages x (A 16KB + B 16KB)
#define STAGE_BYTES 32768
#define B_OFF 16384
#define NSTAGE 3
#define SMEM_DYN (NSTAGE * STAGE_BYTES + 1024)

#define SW128(o) ((o) ^ (((o) >> 3) & 0x70))

// ---------------- device scratch ----------------
__device__ int g_route[NTOK];
__device__ int g_cursor[NOPS];
__device__ int g_base[NOPS];
__device__ int g_cnt[NOPS];
__device__ int g_perm[PERM_SIZE];
__device__ int g_tile_op[MAX_TILES];
__device__ int g_tile_row[MAX_TILES];
__device__ int g_ntiles;

__device__ float g_Wt[NOPS * DIM * DIM];            // tf32-rounded W
__device__ float g_At[(size_t)PERM_SIZE * DIM];     // tf32-rounded, permuted x

// ---------------- PTX helpers ----------------
__device__ __forceinline__ uint32_t smem_u32(const void* p) {
    uint32_t a;
    asm("{ .reg .u64 t; cvta.to.shared.u64 t, %1; cvt.u32.u64 %0, t; }" : "=r"(a) : "l"(p));
    return a;
}
__device__ __forceinline__ void cp_async16(uint32_t dst, const void* src) {
    asm volatile("cp.async.cg.shared.global [%0], [%1], 16;" :: "r"(dst), "l"(src) : "memory");
}
__device__ __forceinline__ void cp_commit() {
    asm volatile("cp.async.commit_group;" ::: "memory");
}
template <int N>
__device__ __forceinline__ void cp_wait() {
    asm volatile("cp.async.wait_group %0;" :: "n"(N) : "memory");
}
__device__ __forceinline__ void ldsm_x4(uint32_t& r0, uint32_t& r1, uint32_t& r2, uint32_t& r3,
                                        uint32_t addr) {
    asm volatile("ldmatrix.sync.aligned.m8n8.x4.shared.b16 {%0,%1,%2,%3}, [%4];"
                 : "=r"(r0), "=r"(r1), "=r"(r2), "=r"(r3) : "r"(addr));
}
__device__ __forceinline__ void mma_tf32(float* c, const uint32_t* a, const uint32_t* b) {
    asm volatile(
        "mma.sync.aligned.m16n8k8.row.col.f32.tf32.tf32.f32 "
        "{%0,%1,%2,%3}, {%4,%5,%6,%7}, {%8,%9}, {%0,%1,%2,%3};"
        : "+f"(c[0]), "+f"(c[1]), "+f"(c[2]), "+f"(c[3])
        : "r"(a[0]), "r"(a[1]), "r"(a[2]), "r"(a[3]), "r"(b[0]), "r"(b[1]));
}
// tf32 destination is a .b32 register (fp32 bit-pattern with low mantissa rounded away)
__device__ __forceinline__ float to_tf32(float x) {
    uint32_t r;
    asm("cvt.rna.tf32.f32 %0, %1;" : "=r"(r) : "f"(x));
    return __uint_as_float(r);
}

// ---------------- aux kernels ----------------

// W -> tf32-rounded fp32 + routing decision
__global__ void wsplit_route_kernel(const float* __restrict__ W,
                                    const float* __restrict__ logits,
                                    const float* __restrict__ gumbel) {
    int i = blockIdx.x * blockDim.x + threadIdx.x;    // 0 .. 524287
    float4 w = ((const float4*)W)[i];
    w.x = to_tf32(w.x); w.y = to_tf32(w.y);
    w.z = to_tf32(w.z); w.w = to_tf32(w.w);
    ((float4*)g_Wt)[i] = w;

    if (i < NTOK) {
        float best = -INFINITY;
        int bi = 0;
#pragma unroll
        for (int k = 0; k < NOPS; k++) {
            float v = logits[i * NOPS + k] + gumbel[i * NOPS + k];
            if (v > best) { best = v; bi = k; }
        }
        g_route[i] = bi;
    }
}

__global__ void scan_kernel() {
    __shared__ int cnt[NOPS * 8];
    __shared__ int s_base[NOPS], s_tb[NOPS + 1], s_cnt[NOPS];
    const int tid = threadIdx.x;
    if (tid < NOPS * 8) cnt[tid] = 0;
    __syncthreads();
    const int rep = (tid & 7) * NOPS;
    for (int t = tid; t < NTOK; t += 256)
        atomicAdd(&cnt[rep + g_route[t]], 1);
    __syncthreads();
    if (tid == 0) {
        int off = 0, tl = 0;
        for (int g = 0; g < NOPS; g++) {
            int c = 0;
            for (int rs = 0; rs < 8; rs++) c += cnt[rs * NOPS + g];
            s_cnt[g] = c; g_cnt[g] = c;
            s_base[g] = off; g_base[g] = off;
            g_cursor[g] = 0;
            s_tb[g] = tl;
            int nt = (c + BM - 1) / BM;
            tl += nt; off += nt * BM;
        }
        s_tb[NOPS] = tl;
        g_ntiles = tl;
    }
    __syncthreads();
    const int ntl = s_tb[NOPS];
    for (int tile = tid; tile < ntl; tile += 256) {
        int g = 0;
        while (tile >= s_tb[g + 1]) g++;
        g_tile_op[tile] = g;
        g_tile_row[tile] = s_base[g] + (tile - s_tb[g]) * BM;
    }
    for (int g = 0; g < NOPS; g++) {
        int c = s_cnt[g];
        int start = s_base[g] + c;
        int end   = s_base[g] + ((c + BM - 1) / BM) * BM;
        for (int p = start + tid; p < end; p += 256) g_perm[p] = -1;
    }
}

// merged scatter + A tf32-convert: one warp per token; extra warps zero padding rows
#define PAD_WARPS 1024
__global__ void scatter_convert_kernel(const float* __restrict__ x) {
    const int w    = (blockIdx.x * blockDim.x + threadIdx.x) >> 5;
    const int lane = threadIdx.x & 31;

    if (w < NTOK) {
        const int t = w;
        int row = 0;
        if (lane == 0) {
            int op  = g_route[t];
            int pos = atomicAdd(&g_cursor[op], 1);
            row = g_base[op] + pos;
            g_perm[row] = t;
        }
        row = __shfl_sync(0xffffffffu, row, 0);
        const float4* src = (const float4*)(x + (size_t)t * DIM);
        float4* dst = (float4*)(g_At + (size_t)row * DIM);
#pragma unroll
        for (int j = 0; j < 4; j++) {
            const int c4 = j * 32 + lane;
            float4 v = src[c4];
            v.x = to_tf32(v.x); v.y = to_tf32(v.y);
            v.z = to_tf32(v.z); v.w = to_tf32(v.w);
            dst[c4] = v;
        }
    } else {
        const int p = w - NTOK;
        if (p >= PAD_WARPS) return;
        const int g = p >> 7, j = p & 127;
        const int cnt  = g_cnt[g];
        const int base = g_base[g];
        const int row  = base + cnt + j;
        const int end  = base + ((cnt + BM - 1) / BM) * BM;
        if (row < end) {
            float4 z = make_float4(0.f, 0.f, 0.f, 0.f);
            float4* dst = (float4*)(g_At + (size_t)row * DIM);
#pragma unroll
            for (int q = 0; q < 4; q++) dst[q * 32 + lane] = z;
        }
    }
}

__device__ __forceinline__ float apply_act(int op, float h) {
    switch (op) {
        case 0:  return 0.5f * h * (1.0f + erff(h * 0.7071067811865476f));
        case 1:  return fmaxf(h, 0.0f);
        case 2:  { float r = fmaxf(h, 0.0f); return r * r; }
        case 3:  return h / (1.0f + expf(-h));
        case 4:  return tanhf(h);
        case 5:  return 1.0f / (1.0f + expf(-h));
        case 6:  return h;
        default: return -h;
    }
}

// ---------------- tf32 MMA grouped GEMM: single pass, 3-stage pipeline ----------------
// 256 threads = 8 warps (2 M x 4 N), warp tile 64x32.
// Chunk = BK=32 tf32 = 128B/row; same SW128 addressing as bf16 path
// (m8k8 tf32 tile == 8x16 b16 ldmatrix tile; fragment maps line up).
__global__ __launch_bounds__(256)
void gemm_kernel(float* __restrict__ out) {
    extern __shared__ char dsm[];
    const int bx = blockIdx.x;
    if (bx >= g_ntiles) return;

    const int op   = g_tile_op[bx];
    const int row0 = g_tile_row[bx];
    const int n0   = blockIdx.y * BN;
    const int tid  = threadIdx.x;
    const int wid  = tid >> 5;
    const int lid  = tid & 31;
    const int wm   = wid >> 2;     // 0..1
    const int wn   = wid & 3;      // 0..3

    char* sbase = (char*)(((uintptr_t)dsm + 1023) & ~(uintptr_t)1023);
    const uint32_t sb = smem_u32(sbase);

    const float* __restrict__ Ag0 = g_At + (size_t)row0 * DIM;
    const float* __restrict__ Bg0 = g_Wt + (size_t)op * DIM * DIM + (size_t)n0 * DIM;

    // store mapping: 1024 16B units per stage half; r = sid>>3 (row), ks = sid&7
    const int lr = tid >> 3;
    const int ks = tid & 7;
    const uint32_t sw_col = (uint32_t)(ks * 16);

    // ldmatrix addressing (identical to bf16 path: 128B rows, SW128)
    const int a_row = wm * 64 + (lid & 15);
    const uint32_t a_rowoff = (uint32_t)(a_row * 128);
    const uint32_t a_mask = (uint32_t)((a_row & 7) << 4);
    const uint32_t a_col0 = (uint32_t)((lid >> 4) << 4);
    const int b_row = wn * 32 + (lid & 7) + ((lid >> 4) << 3);
    const uint32_t b_rowoff = (uint32_t)(B_OFF + b_row * 128);
    const uint32_t b_mask = (uint32_t)((b_row & 7) << 4);
    const uint32_t b_col0 = (uint32_t)(((lid >> 3) & 1) << 4);

    float acc[4][4][4];
#pragma unroll
    for (int i = 0; i < 4; i++)
#pragma unroll
        for (int j = 0; j < 4; j++)
#pragma unroll
            for (int q = 0; q < 4; q++) acc[i][j][q] = 0.0f;

    auto load_chunk = [&](int kc, int s) {
        const float* Ag = Ag0 + kc * BK;
        const float* Bg = Bg0 + kc * BK;
        const uint32_t As = sb + s * STAGE_BYTES;
        const uint32_t Bs = As + B_OFF;
#pragma unroll
        for (int j = 0; j < 4; j++) {
            int r = lr + j * 32;
            uint32_t soff = SW128((uint32_t)(r * 128) + sw_col);
            cp_async16(As + soff, Ag + (size_t)r * DIM + ks * 4);
            cp_async16(Bs + soff, Bg + (size_t)r * DIM + ks * 4);
        }
        cp_commit();
    };

    load_chunk(0, 0);
    load_chunk(1, 1);

    int s = 0;
    for (int i = 0; i < NITER; i++) {
        cp_wait<1>();
        __syncthreads();
        // stage (i+2)%3 was last read at iteration i-1 -> safe to overwrite now
        if (i + 2 < NITER) {
            int s2 = s + 2; if (s2 >= NSTAGE) s2 -= NSTAGE;
            load_chunk(i + 2, s2);
        } else {
            cp_commit();   // keep group count consistent for cp_wait<1>
        }

        const uint32_t stg = sb + s * STAGE_BYTES;
        const uint32_t As_base = stg + a_rowoff;
        const uint32_t Bs_base = stg + b_rowoff;

#pragma unroll
        for (int kk = 0; kk < 4; kk++) {               // 4 x k8 per chunk
            const uint32_t a_col = (a_col0 + kk * 32) ^ a_mask;
            const uint32_t b_col = (b_col0 + kk * 32) ^ b_mask;
            uint32_t a[4][4];
            uint32_t b[4][2];
#pragma unroll
            for (int mi = 0; mi < 4; mi++)
                ldsm_x4(a[mi][0], a[mi][1], a[mi][2], a[mi][3],
                        As_base + mi * (16 * 128) + a_col);
#pragma unroll
            for (int nb = 0; nb < 2; nb++)
                ldsm_x4(b[nb * 2][0], b[nb * 2][1], b[nb * 2 + 1][0], b[nb * 2 + 1][1],
                        Bs_base + nb * (16 * 128) + b_col);
#pragma unroll
            for (int mi = 0; mi < 4; mi++)
#pragma unroll
                for (int ni = 0; ni < 4; ni++)
                    mma_tf32(acc[mi][ni], a[mi], b[ni]);
        }

        if (++s >= NSTAGE) s -= NSTAGE;
    }

    // epilogue: activation + scatter to original token rows
    const int r = lid >> 2;
    const int c = (lid & 3) * 2;
#pragma unroll
    for (int mi = 0; mi < 4; mi++) {
        const int m_lo = wm * 64 + mi * 16 + r;
        const int tok_lo = g_perm[row0 + m_lo];
        const int tok_hi = g_perm[row0 + m_lo + 8];
        float* o_lo = (tok_lo >= 0) ? (out + (size_t)tok_lo * DIM + n0) : nullptr;
        float* o_hi = (tok_hi >= 0) ? (out + (size_t)tok_hi * DIM + n0) : nullptr;
#pragma unroll
        for (int ni = 0; ni < 4; ni++) {
            const int n = wn * 32 + ni * 8 + c;
            if (o_lo) {
                float2 v;
                v.x = apply_act(op, acc[mi][ni][0]);
                v.y = apply_act(op, acc[mi][ni][1]);
                *(float2*)(o_lo + n) = v;
            }
            if (o_hi) {
                float2 v;
                v.x = apply_act(op, acc[mi][ni][2]);
                v.y = apply_act(op, acc[mi][ni][3]);
                *(float2*)(o_hi + n) = v;
            }
        }
    }
}

// ---------------- launch ----------------
extern "C" void kernel_launch(void* const* d_in, const int* in_sizes, int n_in,
                              void* d_out, int out_size) {
    const float* x      = (const float*)d_in[0];
    const float* logits = (const float*)d_in[1];
    const float* gumbel = (const float*)d_in[2];
    const float* W      = (const float*)d_in[3];
    float* out          = (float*)d_out;

    cudaFuncSetAttribute(gemm_kernel, cudaFuncAttributeMaxDynamicSharedMemorySize, SMEM_DYN);

    wsplit_route_kernel<<<(NOPS * DIM * DIM / 4 + 255) / 256, 256>>>(W, logits, gumbel);
    scan_kernel<<<1, 256>>>();
    scatter_convert_kernel<<<((NTOK + PAD_WARPS) * 32) / 256, 256>>>(x);

    dim3 grid(MAX_TILES, DIM / BN);
    gemm_kernel<<<grid, 256, SMEM_DYN>>>(out);
}

// round 13
// speedup vs baseline: 1.7910x; 1.3398x over previous
#include <cuda_runtime.h>
#include <cuda_fp16.h>
#include <math.h>
#include <stdint.h>

// Problem constants
#define NTOK   32768
#define DIM    512
#define NOPS   8

// GEMM tiling: single-pass fp16, BK=64 halfs = 128B/row (SW128 atom)
#define BM 128
#define BN 128
#define BK 64
#define NCHUNK (DIM / BK)      // 8
#define NITER NCHUNK           // single pass
#define MAX_TILES 264
#define PERM_SIZE (MAX_TILES * BM)

// SMEM: 3 stages x (A 16KB + B 16KB)
#define STAGE_BYTES 32768
#define B_OFF 16384
#define NSTAGE 3
#define SMEM_DYN (NSTAGE * STAGE_BYTES + 1024)

#define SW128(o) ((o) ^ (((o) >> 3) & 0x70))

// ---------------- device scratch ----------------
__device__ int g_route[NTOK];
__device__ int g_cursor[NOPS];
__device__ int g_base[NOPS];
__device__ int g_cnt[NOPS];
__device__ int g_perm[PERM_SIZE];
__device__ int g_tile_op[MAX_TILES];
__device__ int g_tile_row[MAX_TILES];
__device__ int g_ntiles;

__device__ __half g_Wh[NOPS * DIM * DIM];           // fp16 W
__device__ __half g_Ah[(size_t)PERM_SIZE * DIM];    // fp16 permuted x

// ---------------- PTX helpers ----------------
__device__ __forceinline__ uint32_t smem_u32(const void* p) {
    uint32_t a;
    asm("{ .reg .u64 t; cvta.to.shared.u64 t, %1; cvt.u32.u64 %0, t; }" : "=r"(a) : "l"(p));
    return a;
}
__device__ __forceinline__ void cp_async16(uint32_t dst, const void* src) {
    asm volatile("cp.async.cg.shared.global [%0], [%1], 16;" :: "r"(dst), "l"(src) : "memory");
}
__device__ __forceinline__ void cp_commit() {
    asm volatile("cp.async.commit_group;" ::: "memory");
}
template <int N>
__device__ __forceinline__ void cp_wait() {
    asm volatile("cp.async.wait_group %0;" :: "n"(N) : "memory");
}
__device__ __forceinline__ void ldsm_x4(uint32_t& r0, uint32_t& r1, uint32_t& r2, uint32_t& r3,
                                        uint32_t addr) {
    asm volatile("ldmatrix.sync.aligned.m8n8.x4.shared.b16 {%0,%1,%2,%3}, [%4];"
                 : "=r"(r0), "=r"(r1), "=r"(r2), "=r"(r3) : "r"(addr));
}
__device__ __forceinline__ void mma_f16(float* c, const uint32_t* a, const uint32_t* b) {
    asm volatile(
        "mma.sync.aligned.m16n8k16.row.col.f32.f16.f16.f32 "
        "{%0,%1,%2,%3}, {%4,%5,%6,%7}, {%8,%9}, {%0,%1,%2,%3};"
        : "+f"(c[0]), "+f"(c[1]), "+f"(c[2]), "+f"(c[3])
        : "r"(a[0]), "r"(a[1]), "r"(a[2]), "r"(a[3]), "r"(b[0]), "r"(b[1]));
}
__device__ __forceinline__ uint32_t pack_h2(float a, float b) {
    __half2 h = __floats2half2_rn(a, b);
    return *(uint32_t*)&h;
}

// ---------------- aux kernels ----------------

// W -> fp16 + routing decision
__global__ void wsplit_route_kernel(const float* __restrict__ W,
                                    const float* __restrict__ logits,
                                    const float* __restrict__ gumbel) {
    int i = blockIdx.x * blockDim.x + threadIdx.x;    // 0 .. 524287
    float4 w = ((const float4*)W)[i];
    uint2 hw;
    hw.x = pack_h2(w.x, w.y);
    hw.y = pack_h2(w.z, w.w);
    *(uint2*)&g_Wh[(size_t)i * 4] = hw;

    if (i < NTOK) {
        float best = -INFINITY;
        int bi = 0;
#pragma unroll
        for (int k = 0; k < NOPS; k++) {
            float v = logits[i * NOPS + k] + gumbel[i * NOPS + k];
            if (v > best) { best = v; bi = k; }
        }
        g_route[i] = bi;
    }
}

__global__ void scan_kernel() {
    __shared__ int cnt[NOPS * 8];
    __shared__ int s_base[NOPS], s_tb[NOPS + 1], s_cnt[NOPS];
    const int tid = threadIdx.x;
    if (tid < NOPS * 8) cnt[tid] = 0;
    __syncthreads();
    const int rep = (tid & 7) * NOPS;
    for (int t = tid; t < NTOK; t += 256)
        atomicAdd(&cnt[rep + g_route[t]], 1);
    __syncthreads();
    if (tid == 0) {
        int off = 0, tl = 0;
        for (int g = 0; g < NOPS; g++) {
            int c = 0;
            for (int rs = 0; rs < 8; rs++) c += cnt[rs * NOPS + g];
            s_cnt[g] = c; g_cnt[g] = c;
            s_base[g] = off; g_base[g] = off;
            g_cursor[g] = 0;
            s_tb[g] = tl;
            int nt = (c + BM - 1) / BM;
            tl += nt; off += nt * BM;
        }
        s_tb[NOPS] = tl;
        g_ntiles = tl;
    }
    __syncthreads();
    const int ntl = s_tb[NOPS];
    for (int tile = tid; tile < ntl; tile += 256) {
        int g = 0;
        while (tile >= s_tb[g + 1]) g++;
        g_tile_op[tile] = g;
        g_tile_row[tile] = s_base[g] + (tile - s_tb[g]) * BM;
    }
    for (int g = 0; g < NOPS; g++) {
        int c = s_cnt[g];
        int start = s_base[g] + c;
        int end   = s_base[g] + ((c + BM - 1) / BM) * BM;
        for (int p = start + tid; p < end; p += 256) g_perm[p] = -1;
    }
}

// merged scatter + A fp16-convert: one warp per token; extra warps zero padding rows
#define PAD_WARPS 1024
__global__ void scatter_convert_kernel(const float* __restrict__ x) {
    const int w    = (blockIdx.x * blockDim.x + threadIdx.x) >> 5;
    const int lane = threadIdx.x & 31;

    if (w < NTOK) {
        const int t = w;
        int row = 0;
        if (lane == 0) {
            int op  = g_route[t];
            int pos = atomicAdd(&g_cursor[op], 1);
            row = g_base[op] + pos;
            g_perm[row] = t;
        }
        row = __shfl_sync(0xffffffffu, row, 0);
        const float4* src = (const float4*)(x + (size_t)t * DIM);
        __half* dst = g_Ah + (size_t)row * DIM;
#pragma unroll
        for (int j = 0; j < 4; j++) {
            const int c4 = j * 32 + lane;
            float4 v = src[c4];
            uint2 hw;
            hw.x = pack_h2(v.x, v.y);
            hw.y = pack_h2(v.z, v.w);
            *(uint2*)(dst + c4 * 4) = hw;
        }
    } else {
        const int p = w - NTOK;
        if (p >= PAD_WARPS) return;
        const int g = p >> 7, j = p & 127;
        const int cnt  = g_cnt[g];
        const int base = g_base[g];
        const int row  = base + cnt + j;
        const int end  = base + ((cnt + BM - 1) / BM) * BM;
        if (row < end) {
            uint2 z = make_uint2(0u, 0u);
            __half* dst = g_Ah + (size_t)row * DIM;
#pragma unroll
            for (int q = 0; q < 4; q++)
                *(uint2*)(dst + (q * 32 + lane) * 4) = z;
        }
    }
}

__device__ __forceinline__ float apply_act(int op, float h) {
    switch (op) {
        case 0:  return 0.5f * h * (1.0f + erff(h * 0.7071067811865476f));
        case 1:  return fmaxf(h, 0.0f);
        case 2:  { float r = fmaxf(h, 0.0f); return r * r; }
        case 3:  return h / (1.0f + expf(-h));
        case 4:  return tanhf(h);
        case 5:  return 1.0f / (1.0f + expf(-h));
        case 6:  return h;
        default: return -h;
    }
}

// ---------------- fp16 MMA grouped GEMM: single pass, 3-stage pipeline ----------------
// 256 threads = 8 warps (2 M x 4 N), warp tile 64x32, BK=64 halfs = 128B/row.
// Identical SW128/ldmatrix addressing to the validated bf16 path.
__global__ __launch_bounds__(256)
void gemm_kernel(float* __restrict__ out) {
    extern __shared__ char dsm[];
    const int bx = blockIdx.x;
    if (bx >= g_ntiles) return;

    const int op   = g_tile_op[bx];
    const int row0 = g_tile_row[bx];
    const int n0   = blockIdx.y * BN;
    const int tid  = threadIdx.x;
    const int wid  = tid >> 5;
    const int lid  = tid & 31;
    const int wm   = wid >> 2;     // 0..1
    const int wn   = wid & 3;      // 0..3

    char* sbase = (char*)(((uintptr_t)dsm + 1023) & ~(uintptr_t)1023);
    const uint32_t sb = smem_u32(sbase);

    const __half* __restrict__ Ag0 = g_Ah + (size_t)row0 * DIM;
    const __half* __restrict__ Bg0 = g_Wh + (size_t)op * DIM * DIM + (size_t)n0 * DIM;

    // store mapping: 1024 16B units per stage half; r = sid>>3 (row), ks = sid&7
    const int lr = tid >> 3;
    const int ks = tid & 7;
    const uint32_t sw_col = (uint32_t)(ks * 16);

    // ldmatrix addressing (identical to bf16 path: 128B rows, SW128)
    const int a_row = wm * 64 + (lid & 15);
    const uint32_t a_rowoff = (uint32_t)(a_row * 128);
    const uint32_t a_mask = (uint32_t)((a_row & 7) << 4);
    const uint32_t a_col0 = (uint32_t)((lid >> 4) << 4);
    const int b_row = wn * 32 + (lid & 7) + ((lid >> 4) << 3);
    const uint32_t b_rowoff = (uint32_t)(B_OFF + b_row * 128);
    const uint32_t b_mask = (uint32_t)((b_row & 7) << 4);
    const uint32_t b_col0 = (uint32_t)(((lid >> 3) & 1) << 4);

    float acc[4][4][4];
#pragma unroll
    for (int i = 0; i < 4; i++)
#pragma unroll
        for (int j = 0; j < 4; j++)
#pragma unroll
            for (int q = 0; q < 4; q++) acc[i][j][q] = 0.0f;

    auto load_chunk = [&](int kc, int s) {
        const __half* Ag = Ag0 + kc * BK;
        const __half* Bg = Bg0 + kc * BK;
        const uint32_t As = sb + s * STAGE_BYTES;
        const uint32_t Bs = As + B_OFF;
#pragma unroll
        for (int j = 0; j < 4; j++) {
            int r = lr + j * 32;
            uint32_t soff = SW128((uint32_t)(r * 128) + sw_col);
            cp_async16(As + soff, Ag + (size_t)r * DIM + ks * 8);
            cp_async16(Bs + soff, Bg + (size_t)r * DIM + ks * 8);
        }
        cp_commit();
    };

    load_chunk(0, 0);
    load_chunk(1, 1);

    int s = 0;
    for (int i = 0; i < NITER; i++) {
        cp_wait<1>();
        __syncthreads();
        // stage (i+2)%3 was last read at iteration i-1 -> safe to overwrite now
        if (i + 2 < NITER) {
            int s2 = s + 2; if (s2 >= NSTAGE) s2 -= NSTAGE;
            load_chunk(i + 2, s2);
        } else {
            cp_commit();   // keep group count consistent for cp_wait<1>
        }

        const uint32_t stg = sb + s * STAGE_BYTES;
        const uint32_t As_base = stg + a_rowoff;
        const uint32_t Bs_base = stg + b_rowoff;

#pragma unroll
        for (int kk = 0; kk < 4; kk++) {               // 4 x k16 per chunk
            const uint32_t a_col = (a_col0 + kk * 32) ^ a_mask;
            const uint32_t b_col = (b_col0 + kk * 32) ^ b_mask;
            uint32_t a[4][4];
            uint32_t b[4][2];
#pragma unroll
            for (int mi = 0; mi < 4; mi++)
                ldsm_x4(a[mi][0], a[mi][1], a[mi][2], a[mi][3],
                        As_base + mi * (16 * 128) + a_col);
#pragma unroll
            for (int nb = 0; nb < 2; nb++)
                ldsm_x4(b[nb * 2][0], b[nb * 2][1], b[nb * 2 + 1][0], b[nb * 2 + 1][1],
                        Bs_base + nb * (16 * 128) + b_col);
#pragma unroll
            for (int mi = 0; mi < 4; mi++)
#pragma unroll
                for (int ni = 0; ni < 4; ni++)
                    mma_f16(acc[mi][ni], a[mi], b[ni]);
        }

        if (++s >= NSTAGE) s -= NSTAGE;
    }

    // epilogue: activation + scatter to original token rows
    const int r = lid >> 2;
    const int c = (lid & 3) * 2;
#pragma unroll
    for (int mi = 0; mi < 4; mi++) {
        const int m_lo = wm * 64 + mi * 16 + r;
        const int tok_lo = g_perm[row0 + m_lo];
        const int tok_hi = g_perm[row0 + m_lo + 8];
        float* o_lo = (tok_lo >= 0) ? (out + (size_t)tok_lo * DIM + n0) : nullptr;
        float* o_hi = (tok_hi >= 0) ? (out + (size_t)tok_hi * DIM + n0) : nullptr;
#pragma unroll
        for (int ni = 0; ni < 4; ni++) {
            const int n = wn * 32 + ni * 8 + c;
            if (o_lo) {
                float2 v;
                v.x = apply_act(op, acc[mi][ni][0]);
                v.y = apply_act(op, acc[mi][ni][1]);
                *(float2*)(o_lo + n) = v;
            }
            if (o_hi) {
                float2 v;
                v.x = apply_act(op, acc[mi][ni][2]);
                v.y = apply_act(op, acc[mi][ni][3]);
                *(float2*)(o_hi + n) = v;
            }
        }
    }
}

// ---------------- launch ----------------
extern "C" void kernel_launch(void* const* d_in, const int* in_sizes, int n_in,
                              void* d_out, int out_size) {
    const float* x      = (const float*)d_in[0];
    const float* logits = (const float*)d_in[1];
    const float* gumbel = (const float*)d_in[2];
    const float* W      = (const float*)d_in[3];
    float* out          = (float*)d_out;

    cudaFuncSetAttribute(gemm_kernel, cudaFuncAttributeMaxDynamicSharedMemorySize, SMEM_DYN);

    wsplit_route_kernel<<<(NOPS * DIM * DIM / 4 + 255) / 256, 256>>>(W, logits, gumbel);
    scan_kernel<<<1, 256>>>();
    scatter_convert_kernel<<<((NTOK + PAD_WARPS) * 32) / 256, 256>>>(x);

    dim3 grid(MAX_TILES, DIM / BN);
    gemm_kernel<<<grid, 256, SMEM_DYN>>>(out);
}